// round 4
// baseline (speedup 1.0000x reference)
#include <cuda_runtime.h>
#include <cstdint>

// out[s, r, j] = in[r, idx[s] + j]
// in:  (n_rows=131072, FEAT=512) fp32
// idx: (NUM_SLICES=16,) int32, values in [0, 448)
// out: (16, n_rows, 64) fp32
//
// Each CTA handles ROWS_PER_CTA=2 input rows: stage 2x2KB rows in smem
// (coalesced float2 loads), then each of the 256 threads emits one float4
// per row for its (slice, quad) assignment. DRAM read = 256 MB (each row
// exactly once), write = 512 MB. Pure HBM-bound; predicted ~110-135 us.

#define FEAT 512
#define NUM_SLICES 16
#define SLICE_LEN 64
#define ROWS_PER_CTA 2

__global__ __launch_bounds__(256) void fuse_slice_kernel(
    const float* __restrict__ in,
    const int* __restrict__ idx,
    float* __restrict__ out,
    int n_rows)
{
    __shared__ float row[ROWS_PER_CTA][FEAT];
    __shared__ int sidx[NUM_SLICES];

    const int r0 = blockIdx.x * ROWS_PER_CTA;
    const int t = threadIdx.x;

    // Stage both rows: 256 threads x float2 per row, fully coalesced.
    #pragma unroll
    for (int k = 0; k < ROWS_PER_CTA; k++) {
        if (r0 + k < n_rows) {
            reinterpret_cast<float2*>(row[k])[t] =
                reinterpret_cast<const float2*>(in + (size_t)(r0 + k) * FEAT)[t];
        }
    }

    if (t < NUM_SLICES) sidx[t] = idx[t];
    __syncthreads();

    // thread t -> slice s = t>>4, quad v = (t&15)*4
    const int s = t >> 4;
    const int v = (t & 15) << 2;
    const int base = sidx[s] + v;

    #pragma unroll
    for (int k = 0; k < ROWS_PER_CTA; k++) {
        if (r0 + k < n_rows) {
            float4 val;
            val.x = row[k][base + 0];
            val.y = row[k][base + 1];
            val.z = row[k][base + 2];
            val.w = row[k][base + 3];

            // out offset: ((s * n_rows + (r0+k)) * 64 + v)
            const size_t o = (((size_t)s * n_rows + (r0 + k)) << 6) + (size_t)v;
            *reinterpret_cast<float4*>(out + o) = val;
        }
    }
}

extern "C" void kernel_launch(void* const* d_in, const int* in_sizes, int n_in,
                              void* d_out, int out_size)
{
    const float* in  = (const float*)d_in[0];
    const int*   idx = (const int*)d_in[1];
    float*       out = (float*)d_out;

    const int n_rows = in_sizes[0] / FEAT;   // 131072

    const int grid = (n_rows + ROWS_PER_CTA - 1) / ROWS_PER_CTA;
    fuse_slice_kernel<<<grid, 256>>>(in, idx, out, n_rows);
}

// round 5
// speedup vs baseline: 1.0240x; 1.0240x over previous
#include <cuda_runtime.h>
#include <cstdint>

// out[s, r, j] = in[r, idx[s] + j]
// in:  (n_rows=131072, FEAT=512) fp32 ; idx: (16,) int32 in [0,448) ; out: (16, n_rows, 64) fp32
//
// 4 rows per CTA staged in smem via LDG.128 (2 independent float4 loads/thread),
// with staging loads PREDICATED on slice coverage: float4 chunks of the row not
// touched by any of the 16 slices are never fetched (~8% read-traffic savings).
// Store phase: thread t -> slice s=t>>4, quad v=(t&15)*4, one STG.128 per row.
// Writes are 256B-contiguous, 128B-aligned, full-sector (no RFO).

#define FEAT 512
#define NUM_SLICES 16
#define SLICE_LEN 64
#define RPC 4   // rows per CTA

__global__ __launch_bounds__(256) void fuse_slice_kernel(
    const float* __restrict__ in,
    const int* __restrict__ idx,
    float* __restrict__ out,
    int n_rows)
{
    __shared__ float row[RPC][FEAT];
    __shared__ int sidx[NUM_SLICES];

    const int t = threadIdx.x;
    const size_t r0 = (size_t)blockIdx.x * RPC;

    if (t < NUM_SLICES) sidx[t] = idx[t];
    __syncthreads();

    // ---- staging: 512 float4 chunks per CTA, 2 per thread.
    // chunk c = t + 256*i covers row k = c>>7, float4-index c4 = c&127.
    // Both chunks of a thread share c4 = t&127 -> compute coverage once.
    const int c4  = t & 127;
    const int col = c4 << 2;

    bool need = false;
    #pragma unroll
    for (int s = 0; s < NUM_SLICES; s++) {
        const int b = sidx[s];
        need |= (b <= col + 3) && (b + SLICE_LEN > col);
    }

    const int k0 = t >> 7;  // 0 or 1; second chunk is row k0+2
    if (need) {
        #pragma unroll
        for (int i = 0; i < 2; i++) {
            const int k = k0 + 2 * i;
            if (r0 + k < (size_t)n_rows) {
                reinterpret_cast<float4*>(row[k])[c4] =
                    reinterpret_cast<const float4*>(in + (r0 + k) * FEAT)[c4];
            }
        }
    }
    __syncthreads();

    // ---- emit: thread t -> slice s, quad v; one float4 store per row.
    const int s = t >> 4;
    const int v = (t & 15) << 2;
    const int base = sidx[s] + v;

    #pragma unroll
    for (int k = 0; k < RPC; k++) {
        if (r0 + k < (size_t)n_rows) {
            float4 val;
            val.x = row[k][base + 0];
            val.y = row[k][base + 1];
            val.z = row[k][base + 2];
            val.w = row[k][base + 3];

            const size_t o = (((size_t)s * n_rows + (r0 + k)) << 6) + (size_t)v;
            *reinterpret_cast<float4*>(out + o) = val;
        }
    }
}

extern "C" void kernel_launch(void* const* d_in, const int* in_sizes, int n_in,
                              void* d_out, int out_size)
{
    const float* in  = (const float*)d_in[0];
    const int*   idx = (const int*)d_in[1];
    float*       out = (float*)d_out;

    const int n_rows = in_sizes[0] / FEAT;   // 131072

    const int grid = (n_rows + RPC - 1) / RPC;
    fuse_slice_kernel<<<grid, 256>>>(in, idx, out, n_rows);
}